// round 17
// baseline (speedup 1.0000x reference)
#include <cuda_runtime.h>
#include <cuda_bf16.h>
#include <cstdint>

// ---------------------------------------------------------------------------
// SlidingWindowAttention on GB300 (sm_103 base target — no tcgen05)
// R16: R15's 4-stage BK=16 cp.async GEMM pipeline with the pitch fixed to a
//      16B multiple (48) — R15's PIT=40 broke cp.async/ldmatrix alignment.
//      HMMA flash attention (R14) unchanged.
// ---------------------------------------------------------------------------

constexpr int BB  = 2;
constexpr int SS  = 2048;
constexpr int NH  = 16;
constexpr int HDm = 64;
constexpr int DM  = 1024;      // NH*HDm
constexpr int ND3 = 3072;      // 3*DM
constexpr int WIN = 512;
constexpr int MT  = BB * SS;   // 4096 rows

// Scratch (device globals: allocation-free)
__device__ __nv_bfloat16 g_Qhi[BB * NH * SS * HDm];
__device__ __nv_bfloat16 g_Qlo[BB * NH * SS * HDm];
__device__ __nv_bfloat16 g_Khi[BB * NH * SS * HDm];
__device__ __nv_bfloat16 g_Klo[BB * NH * SS * HDm];
__device__ __nv_bfloat16 g_Vhi[BB * NH * SS * HDm];
__device__ __nv_bfloat16 g_Vlo[BB * NH * SS * HDm];
__device__ __nv_bfloat16 g_Ahi [MT * DM];
__device__ __nv_bfloat16 g_Alo [MT * DM];
__device__ __nv_bfloat16 g_AOhi[MT * DM];
__device__ __nv_bfloat16 g_AOlo[MT * DM];
__device__ __nv_bfloat16 g_Bqhi[ND3 * DM];
__device__ __nv_bfloat16 g_Bqlo[ND3 * DM];
__device__ __nv_bfloat16 g_Bohi[DM * DM];
__device__ __nv_bfloat16 g_Bolo[DM * DM];

// ============================= MMA helpers =================================
#define LDSM_X4(R, addr)                                                      \
    asm volatile("ldmatrix.sync.aligned.m8n8.x4.shared.b16 {%0,%1,%2,%3}, [%4];" \
        : "=r"((R)[0]), "=r"((R)[1]), "=r"((R)[2]), "=r"((R)[3]) : "r"(addr))

#define LDSM_X4_T(R, addr)                                                    \
    asm volatile("ldmatrix.sync.aligned.m8n8.x4.trans.shared.b16 {%0,%1,%2,%3}, [%4];" \
        : "=r"((R)[0]), "=r"((R)[1]), "=r"((R)[2]), "=r"((R)[3]) : "r"(addr))

#define MMA16816(C, A, b0, b1)                                                \
    asm volatile("mma.sync.aligned.m16n8k16.row.col.f32.bf16.bf16.f32 "       \
        "{%0,%1,%2,%3},{%4,%5,%6,%7},{%8,%9},{%0,%1,%2,%3};"                  \
        : "+f"((C)[0]), "+f"((C)[1]), "+f"((C)[2]), "+f"((C)[3])              \
        : "r"((A)[0]), "r"((A)[1]), "r"((A)[2]), "r"((A)[3]), "r"(b0), "r"(b1))

#define CP_ASYNC16(dst_u32, src_ptr)                                          \
    asm volatile("cp.async.cg.shared.global [%0], [%1], 16;"                  \
        :: "r"(dst_u32), "l"(src_ptr))
#define CP_COMMIT() asm volatile("cp.async.commit_group;" ::: "memory")
#define CP_WAIT0()  asm volatile("cp.async.wait_group 0;" ::: "memory")
#define CP_WAIT2()  asm volatile("cp.async.wait_group 2;" ::: "memory")

__device__ __forceinline__ uint32_t smem_u32(const void* p) {
    uint32_t a;
    asm("{ .reg .u64 t; cvta.to.shared.u64 t, %1; cvt.u32.u64 %0, t; }"
        : "=r"(a) : "l"(p));
    return a;
}

// ============================ split helpers ================================
__device__ __forceinline__ void split_bf16(float x, __nv_bfloat16& hi, __nv_bfloat16& lo) {
    hi = __float2bfloat16_rn(x);
    lo = __float2bfloat16_rn(x - __bfloat162float(hi));
}
__device__ __forceinline__ void split2(float a, float b, uint32_t& hi, uint32_t& lo) {
    __nv_bfloat162 h2, l2;
    split_bf16(a, h2.x, l2.x);
    split_bf16(b, h2.y, l2.y);
    hi = *reinterpret_cast<uint32_t*>(&h2);
    lo = *reinterpret_cast<uint32_t*>(&l2);
}

// ========================= conversion kernels ==============================
__global__ __launch_bounds__(256) void conv_x(const float* __restrict__ X,
                                              __nv_bfloat16* __restrict__ Ahi,
                                              __nv_bfloat16* __restrict__ Alo)
{
    const int idx = blockIdx.x * 256 + threadIdx.x;
    const int m  = idx >> 8;
    const int c  = (idx & 255) * 4;
    float4 v = *(const float4*)(X + m * DM + c);
    uint32_t h01, l01, h23, l23;
    split2(v.x, v.y, h01, l01);
    split2(v.z, v.w, h23, l23);
    *(uint32_t*)(Ahi + (size_t)m * DM + c)     = h01;
    *(uint32_t*)(Ahi + (size_t)m * DM + c + 2) = h23;
    *(uint32_t*)(Alo + (size_t)m * DM + c)     = l01;
    *(uint32_t*)(Alo + (size_t)m * DM + c + 2) = l23;
}

__global__ __launch_bounds__(256) void conv_w(const float* __restrict__ W,
                                              __nv_bfloat16* __restrict__ Bhi,
                                              __nv_bfloat16* __restrict__ Blo,
                                              int Nn)
{
    __shared__ float t[32][33];
    const int tx = threadIdx.x, ty = threadIdx.y;
    const int n0 = blockIdx.x * 32, k0 = blockIdx.y * 32;
#pragma unroll
    for (int i = 0; i < 32; i += 8)
        t[ty + i][tx] = W[(size_t)(k0 + ty + i) * Nn + n0 + tx];
    __syncthreads();
#pragma unroll
    for (int i = 0; i < 32; i += 8) {
        const int n = n0 + ty + i;
        const float v = t[tx][ty + i];
        __nv_bfloat16 hi, lo;
        split_bf16(v, hi, lo);
        Bhi[(size_t)n * DM + k0 + tx] = hi;
        Blo[(size_t)n * DM + k0 + tx] = lo;
    }
}

// ======================= HMMA bf16 GEMM (4-stage BK=16) ====================
// C[M=4096][N] = (Ahi+Alo) @ (Bhi+Blo)^T + bias  ≈ hh + lh + hl
// 128x128 CTA tile, 8 warps (4m x 2n). BK=16 chunks (64), 4-stage cp.async
// pipeline with wait_group<=2, 2 CTAs/SM. Pitch 48B (16B-aligned, and
// 48*r mod 128 covers 8 distinct offsets -> conflict-free LDSM phases).
constexpr int PIT   = 48;                // bytes per 16-bf16 row (32B + 16 pad)
constexpr int NCH   = DM / 16;           // 64 chunks
constexpr int TILE  = 128 * PIT;         // 6144 B
constexpr int OFF_ALO = TILE;
constexpr int OFF_BHI = 2 * TILE;
constexpr int OFF_BLO = 3 * TILE;
constexpr int STG   = 4 * TILE;          // 24576 B per stage
constexpr int NSTAGE = 4;
constexpr int TG_SMEM = NSTAGE * STG;    // 98304 B

template <int EPI>
__global__ __launch_bounds__(256, 2) void tgemm(const __nv_bfloat16* __restrict__ Ahi,
                                                const __nv_bfloat16* __restrict__ Alo,
                                                const __nv_bfloat16* __restrict__ Bhi,
                                                const __nv_bfloat16* __restrict__ Blo,
                                                const float* __restrict__ bias,
                                                float* __restrict__ Cout)
{
    extern __shared__ __align__(16) char smem[];
    const uint32_t sbase = smem_u32(smem);

    const int tid  = threadIdx.x;
    const int wid  = tid >> 5;
    const int lane = tid & 31;
    const int wm   = wid >> 1;
    const int wn   = wid & 1;
    const int n0   = blockIdx.x * 128;
    const int m0   = blockIdx.y * 128;

    // cp.async staging: per tile 128 rows x 32B; thread -> (row=tid/2, half=tid&1)
    const int ldRow = tid >> 1;
    const int ldC   = (tid & 1) * 16;
    const char* gAh = (const char*)(Ahi + (size_t)(m0 + ldRow) * DM) + ldC;
    const char* gAl = (const char*)(Alo + (size_t)(m0 + ldRow) * DM) + ldC;
    const char* gBh = (const char*)(Bhi + (size_t)(n0 + ldRow) * DM) + ldC;
    const char* gBl = (const char*)(Blo + (size_t)(n0 + ldRow) * DM) + ldC;
    const uint32_t rowOff = ldRow * PIT + ldC;

    // ldmatrix lane addresses (byte offsets within a tile) — all 16B-aligned
    const int aOff0 = (wm * 32 +      (lane & 15)) * PIT + (lane >> 4) * 16;
    const int aOff1 = aOff0 + 16 * PIT;
    const int bRow  = wn * 64 + (lane & 7) + ((lane >> 4) << 3);
    const int bCol  = ((lane >> 3) & 1) * 16;
    int bOff[4];
#pragma unroll
    for (int bt = 0; bt < 4; bt++)
        bOff[bt] = (bRow + bt * 16) * PIT + bCol;

    float c[2][8][4];
#pragma unroll
    for (int mt = 0; mt < 2; mt++)
#pragma unroll
        for (int nt = 0; nt < 8; nt++)
#pragma unroll
            for (int r = 0; r < 4; r++) c[mt][nt][r] = 0.f;

    auto issue_stage = [&](int ch, int s) {
        const uint32_t base = sbase + s * STG;
        const int kb = ch * 32;              // byte offset into K
        CP_ASYNC16(base + rowOff,           gAh + kb);
        CP_ASYNC16(base + OFF_ALO + rowOff, gAl + kb);
        CP_ASYNC16(base + OFF_BHI + rowOff, gBh + kb);
        CP_ASYNC16(base + OFF_BLO + rowOff, gBl + kb);
        CP_COMMIT();
    };

    issue_stage(0, 0);
    issue_stage(1, 1);
    issue_stage(2, 2);

    int s = 0;
    for (int ch = 0; ch < NCH; ch++) {
        CP_WAIT2();            // stage ch resident; ch+1, ch+2 may be in flight
        __syncthreads();       // all warps done with stage (ch-1); slot reusable
        if (ch + 3 < NCH) {
            const int sn = (s + 3 >= NSTAGE) ? s + 3 - NSTAGE : s + 3;
            issue_stage(ch + 3, sn);
        }

        const uint32_t sb = sbase + s * STG;
        uint32_t ah[2][4], bh[4][4];
        LDSM_X4(ah[0], sb + aOff0);
        LDSM_X4(ah[1], sb + aOff1);
#pragma unroll
        for (int bt = 0; bt < 4; bt++)
            LDSM_X4(bh[bt], sb + OFF_BHI + bOff[bt]);
#pragma unroll
        for (int mt = 0; mt < 2; mt++)
#pragma unroll
            for (int nt = 0; nt < 8; nt++)
                MMA16816(c[mt][nt], ah[mt],
                         bh[nt >> 1][(nt & 1) * 2 + 0],
                         bh[nt >> 1][(nt & 1) * 2 + 1]);
        {
            uint32_t al[2][4];
            LDSM_X4(al[0], sb + OFF_ALO + aOff0);
            LDSM_X4(al[1], sb + OFF_ALO + aOff1);
#pragma unroll
            for (int mt = 0; mt < 2; mt++)
#pragma unroll
                for (int nt = 0; nt < 8; nt++)
                    MMA16816(c[mt][nt], al[mt],
                             bh[nt >> 1][(nt & 1) * 2 + 0],
                             bh[nt >> 1][(nt & 1) * 2 + 1]);
        }
        {
            uint32_t bl[4][4];
#pragma unroll
            for (int bt = 0; bt < 4; bt++)
                LDSM_X4(bl[bt], sb + OFF_BLO + bOff[bt]);
#pragma unroll
            for (int mt = 0; mt < 2; mt++)
#pragma unroll
                for (int nt = 0; nt < 8; nt++)
                    MMA16816(c[mt][nt], ah[mt],
                             bl[nt >> 1][(nt & 1) * 2 + 0],
                             bl[nt >> 1][(nt & 1) * 2 + 1]);
        }
        s = (s + 1 >= NSTAGE) ? 0 : s + 1;
    }

    // ---- epilogue ----
    const int g  = lane >> 2;
    const int tg = lane & 3;
#pragma unroll
    for (int mt = 0; mt < 2; mt++) {
#pragma unroll
        for (int half = 0; half < 2; half++) {
            const int m = m0 + wm * 32 + mt * 16 + g + half * 8;
            if (EPI == 0) {
                const int which = n0 >> 10;        // uniform per CTA
                __nv_bfloat16* dh = (which == 0) ? g_Qhi : (which == 1) ? g_Khi : g_Vhi;
                __nv_bfloat16* dl = (which == 0) ? g_Qlo : (which == 1) ? g_Klo : g_Vlo;
                const float scl = (which == 0) ? 0.125f : 1.0f;  // fold 1/sqrt(hd)
                const int bb = m >> 11;
                const int ss = m & (SS - 1);
#pragma unroll
                for (int nt = 0; nt < 8; nt++) {
                    const int n = n0 + wn * 64 + nt * 8 + tg * 2;
                    const int hh = (n & (DM - 1)) >> 6;
                    const int d0 = n & 63;
                    const float vx = (c[mt][nt][half * 2 + 0] + bias[n + 0]) * scl;
                    const float vy = (c[mt][nt][half * 2 + 1] + bias[n + 1]) * scl;
                    uint32_t hi, lo;
                    split2(vx, vy, hi, lo);
                    const size_t off = ((size_t)(bb * NH + hh) * SS + ss) * HDm + d0;
                    *(uint32_t*)(dh + off) = hi;
                    *(uint32_t*)(dl + off) = lo;
                }
            } else {
#pragma unroll
                for (int nt = 0; nt < 8; nt++) {
                    const int n = n0 + wn * 64 + nt * 8 + tg * 2;
                    float2 v;
                    v.x = c[mt][nt][half * 2 + 0] + bias[n + 0];
                    v.y = c[mt][nt][half * 2 + 1] + bias[n + 1];
                    *(float2*)(Cout + (size_t)m * DM + n) = v;
                }
            }
        }
    }
}

// ===================== HMMA flash attention (R14) ==========================
constexpr int APQ   = 144;
constexpr int AQH   = 0;
constexpr int AQL   = 64 * APQ;
constexpr int ASTG0 = 2 * 64 * APQ;
constexpr int A_KH  = 0;
constexpr int A_KL  = 64 * APQ;
constexpr int A_VH  = 2 * 64 * APQ;
constexpr int A_VL  = 3 * 64 * APQ;
constexpr int ASTG  = 4 * 64 * APQ;
constexpr int ATTN_SMEM = ASTG0 + 2 * ASTG;  // 92160

__global__ __launch_bounds__(128) void attn_mma()
{
    extern __shared__ __align__(16) char sm[];
    const uint32_t sb = smem_u32(sm);
    const int tid  = threadIdx.x;
    const int w    = tid >> 5;
    const int lane = tid & 31;
    const int g    = lane >> 2;
    const int tg   = lane & 3;
    const int q0   = blockIdx.x * 64;
    const int h    = blockIdx.y;
    const int b    = blockIdx.z;

    const size_t hoff = (size_t)(b * NH + h) * SS * HDm;
    const char* Kh = (const char*)(g_Khi + hoff);
    const char* Kl = (const char*)(g_Klo + hoff);
    const char* Vh = (const char*)(g_Vhi + hoff);
    const char* Vl = (const char*)(g_Vlo + hoff);

    auto cp_tile = [&](uint32_t dst, const char* src) {
#pragma unroll
        for (int i = 0; i < 4; i++) {
            const int c  = tid + i * 128;
            const int r  = c >> 3;
            const int cc = (c & 7) * 16;
            CP_ASYNC16(dst + r * APQ + cc, src + r * 128 + cc);
        }
    };
    auto issue_kv = [&](int s, int kb) {
        const uint32_t base = sb + ASTG0 + s * ASTG;
        const size_t boff = (size_t)kb * 8192;
        cp_tile(base + A_KH, Kh + boff);
        cp_tile(base + A_KL, Kl + boff);
        cp_tile(base + A_VH, Vh + boff);
        cp_tile(base + A_VL, Vl + boff);
        CP_COMMIT();
    };

    const int kb_start = (q0 >= WIN) ? ((q0 - (WIN - 1)) >> 6) : 0;
    const int kb_end   = q0 >> 6;

    cp_tile(sb + AQH, (const char*)(g_Qhi + hoff) + (size_t)q0 * 128);
    cp_tile(sb + AQL, (const char*)(g_Qlo + hoff) + (size_t)q0 * 128);
    issue_kv(0, kb_start);
    CP_WAIT0();
    __syncthreads();

    uint32_t qh[4][4], ql[4][4];
    const uint32_t qoff = (uint32_t)((w * 16 + (lane & 15)) * APQ + (lane >> 4) * 16);
#pragma unroll
    for (int ks = 0; ks < 4; ks++) {
        LDSM_X4(qh[ks], sb + AQH + qoff + ks * 32);
        LDSM_X4(ql[ks], sb + AQL + qoff + ks * 32);
    }

    float o[8][4];
#pragma unroll
    for (int nd = 0; nd < 8; nd++)
#pragma unroll
        for (int r = 0; r < 4; r++) o[nd][r] = 0.f;
    float m0 = -1e30f, m1 = -1e30f, l0 = 0.f, l1 = 0.f;

    const uint32_t kRowOff = (uint32_t)(((lane & 7) + ((lane >> 4) << 3)) * APQ
                                        + ((lane >> 3) & 1) * 16);
    const uint32_t vRowOff = (uint32_t)(((lane & 7) + (((lane >> 3) & 1) << 3)) * APQ
                                        + (lane >> 4) * 16);

    const int r0 = q0 + w * 16 + g;
    const int r1 = r0 + 8;

    int s = 0;
    for (int kb = kb_start; kb <= kb_end; kb++) {
        if (kb < kb_end) issue_kv(s ^ 1, kb + 1);
        const uint32_t stg = sb + ASTG0 + s * ASTG;

        float sc[8][4];
#pragma unroll
        for (int nt = 0; nt < 8; nt++)
#pragma unroll
            for (int r = 0; r < 4; r++) sc[nt][r] = 0.f;

#pragma unroll
        for (int ks = 0; ks < 4; ks++) {
            const uint32_t ko = ks * 32;
            uint32_t kh4[4][4];
#pragma unroll
            for (int kg = 0; kg < 4; kg++)
                LDSM_X4(kh4[kg], stg + A_KH + kg * (16 * APQ) + kRowOff + ko);
#pragma unroll
            for (int kg = 0; kg < 4; kg++) {
                MMA16816(sc[kg * 2 + 0], qh[ks], kh4[kg][0], kh4[kg][1]);
                MMA16816(sc[kg * 2 + 1], qh[ks], kh4[kg][2], kh4[kg][3]);
                MMA16816(sc[kg * 2 + 0], ql[ks], kh4[kg][0], kh4[kg][1]);
                MMA16816(sc[kg * 2 + 1], ql[ks], kh4[kg][2], kh4[kg][3]);
            }
#pragma unroll
            for (int kg = 0; kg < 4; kg++) {
                uint32_t kl4[4];
                LDSM_X4(kl4, stg + A_KL + kg * (16 * APQ) + kRowOff + ko);
                MMA16816(sc[kg * 2 + 0], qh[ks], kl4[0], kl4[1]);
                MMA16816(sc[kg * 2 + 1], qh[ks], kl4[2], kl4[3]);
            }
        }

        const int diff = q0 - kb * 64;
        const bool full = (diff >= 63) && (diff + 63 < WIN);
        if (!full) {
#pragma unroll
            for (int nt = 0; nt < 8; nt++) {
#pragma unroll
                for (int cc = 0; cc < 2; cc++) {
                    const int key = kb * 64 + nt * 8 + 2 * tg + cc;
                    const int d0 = r0 - key;
                    const int d1 = r1 - key;
                    if (d0 < 0 || d0 >= WIN) sc[nt][cc]     = -1e30f;
                    if (d1 < 0 || d1 >= WIN) sc[nt][2 + cc] = -1e30f;
                }
            }
        }
        float mx0 = -1e30f, mx1 = -1e30f;
#pragma unroll
        for (int nt = 0; nt < 8; nt++) {
            mx0 = fmaxf(mx0, fmaxf(sc[nt][0], sc[nt][1]));
            mx1 = fmaxf(mx1, fmaxf(sc[nt][2], sc[nt][3]));
        }
        mx0 = fmaxf(mx0, __shfl_xor_sync(0xffffffffu, mx0, 1));
        mx0 = fmaxf(mx0, __shfl_xor_sync(0xffffffffu, mx0, 2));
        mx1 = fmaxf(mx1, __shfl_xor_sync(0xffffffffu, mx1, 1));
        mx1 = fmaxf(mx1, __shfl_xor_sync(0xffffffffu, mx1, 2));

        const float mn0 = fmaxf(m0, mx0);
        const float mn1 = fmaxf(m1, mx1);
        const float c0 = __expf(m0 - mn0);
        const float c1 = __expf(m1 - mn1);

        float ps0 = 0.f, ps1 = 0.f;
#pragma unroll
        for (int nt = 0; nt < 8; nt++) {
            sc[nt][0] = (sc[nt][0] > -1e29f) ? __expf(sc[nt][0] - mn0) : 0.f;
            sc[nt][1] = (sc[nt][1] > -1e29f) ? __expf(sc[nt][1] - mn0) : 0.f;
            sc[nt][2] = (sc[nt][2] > -1e29f) ? __expf(sc[nt][2] - mn1) : 0.f;
            sc[nt][3] = (sc[nt][3] > -1e29f) ? __expf(sc[nt][3] - mn1) : 0.f;
            ps0 += sc[nt][0] + sc[nt][1];
            ps1 += sc[nt][2] + sc[nt][3];
        }
        ps0 += __shfl_xor_sync(0xffffffffu, ps0, 1);
        ps0 += __shfl_xor_sync(0xffffffffu, ps0, 2);
        ps1 += __shfl_xor_sync(0xffffffffu, ps1, 1);
        ps1 += __shfl_xor_sync(0xffffffffu, ps1, 2);

        l0 = l0 * c0 + ps0;  m0 = mn0;
        l1 = l1 * c1 + ps1;  m1 = mn1;
#pragma unroll
        for (int nd = 0; nd < 8; nd++) {
            o[nd][0] *= c0; o[nd][1] *= c0;
            o[nd][2] *= c1; o[nd][3] *= c1;
        }

#pragma unroll
        for (int j = 0; j < 4; j++) {
            uint32_t ph[4], pl[4];
            split2(sc[2*j][0],   sc[2*j][1],   ph[0], pl[0]);
            split2(sc[2*j][2],   sc[2*j][3],   ph[1], pl[1]);
            split2(sc[2*j+1][0], sc[2*j+1][1], ph[2], pl[2]);
            split2(sc[2*j+1][2], sc[2*j+1][3], ph[3], pl[3]);
#pragma unroll
            for (int dg = 0; dg < 4; dg++) {
                uint32_t vh4[4], vl4[4];
                LDSM_X4_T(vh4, stg + A_VH + j * (16 * APQ) + vRowOff + dg * 32);
                LDSM_X4_T(vl4, stg + A_VL + j * (16 * APQ) + vRowOff + dg * 32);
                MMA16816(o[dg * 2 + 0], ph, vh4[0], vh4[1]);
                MMA16816(o[dg * 2 + 1], ph, vh4[2], vh4[3]);
                MMA16816(o[dg * 2 + 0], pl, vh4[0], vh4[1]);
                MMA16816(o[dg * 2 + 1], pl, vh4[2], vh4[3]);
                MMA16816(o[dg * 2 + 0], ph, vl4[0], vl4[1]);
                MMA16816(o[dg * 2 + 1], ph, vl4[2], vl4[3]);
            }
        }

        if (kb < kb_end) { CP_WAIT0(); __syncthreads(); }
        s ^= 1;
    }

    const float i0 = 1.f / l0;
    const float i1 = 1.f / l1;
#pragma unroll
    for (int nd = 0; nd < 8; nd++) {
        const size_t base0 = (size_t)(b * SS + r0) * DM + h * 64 + nd * 8 + 2 * tg;
        const size_t base1 = base0 + (size_t)8 * DM;
        uint32_t hi, lo;
        split2(o[nd][0] * i0, o[nd][1] * i0, hi, lo);
        *(uint32_t*)(g_AOhi + base0) = hi;
        *(uint32_t*)(g_AOlo + base0) = lo;
        split2(o[nd][2] * i1, o[nd][3] * i1, hi, lo);
        *(uint32_t*)(g_AOhi + base1) = hi;
        *(uint32_t*)(g_AOlo + base1) = lo;
    }
}

// ---------------------------------------------------------------------------
extern "C" void kernel_launch(void* const* d_in, const int* in_sizes, int n_in,
                              void* d_out, int out_size)
{
    const float* x     = (const float*)d_in[0];
    const float* qkvw  = (const float*)d_in[1];
    const float* qkvb  = (const float*)d_in[2];
    const float* outw  = (const float*)d_in[3];
    const float* outb  = (const float*)d_in[4];
    float* out = (float*)d_out;

    cudaFuncSetAttribute(attn_mma, cudaFuncAttributeMaxDynamicSharedMemorySize,
                         ATTN_SMEM);
    cudaFuncSetAttribute(tgemm<0>, cudaFuncAttributeMaxDynamicSharedMemorySize, TG_SMEM);
    cudaFuncSetAttribute(tgemm<1>, cudaFuncAttributeMaxDynamicSharedMemorySize, TG_SMEM);

    __nv_bfloat16 *Ahi, *Alo, *AOhi, *AOlo, *Bqhi, *Bqlo, *Bohi, *Bolo;
    cudaGetSymbolAddress((void**)&Ahi,  g_Ahi);
    cudaGetSymbolAddress((void**)&Alo,  g_Alo);
    cudaGetSymbolAddress((void**)&AOhi, g_AOhi);
    cudaGetSymbolAddress((void**)&AOlo, g_AOlo);
    cudaGetSymbolAddress((void**)&Bqhi, g_Bqhi);
    cudaGetSymbolAddress((void**)&Bqlo, g_Bqlo);
    cudaGetSymbolAddress((void**)&Bohi, g_Bohi);
    cudaGetSymbolAddress((void**)&Bolo, g_Bolo);

    // 0) split-precision conversions
    conv_x<<<MT * DM / 1024, 256>>>(x, Ahi, Alo);
    conv_w<<<dim3(ND3 / 32, DM / 32), dim3(32, 8)>>>(qkvw, Bqhi, Bqlo, ND3);
    conv_w<<<dim3(DM  / 32, DM / 32), dim3(32, 8)>>>(outw, Bohi, Bolo, DM);

    // 1) QKV projection -> pre-split bf16 Q/K/V (Q scaled by 1/8)
    tgemm<0><<<dim3(ND3 / 128, MT / 128), 256, TG_SMEM>>>(Ahi, Alo, Bqhi, Bqlo,
                                                          qkvb, nullptr);

    // 2) Windowed attention on HMMA, writes split-bf16 AO
    attn_mma<<<dim3(SS / 64, NH, BB), 128, ATTN_SMEM>>>();

    // 3) Output projection (bf16 HMMA 3-product)
    tgemm<1><<<dim3(DM / 128, MT / 128), 256, TG_SMEM>>>(AOhi, AOlo, Bohi, Bolo,
                                                         outb, out);
}